// round 4
// baseline (speedup 1.0000x reference)
#include <cuda_runtime.h>
#include <math.h>

// Problem constants
#define S_N 16
#define B_N 128
#define T_N 200
#define L_N 64
#define R_N 16
#define H_N 256
#define NT  256
#define LP  65            // padded row stride for 64x64 matrices (conflict-free column reads)
#define TRI (L_N*(L_N+1)/2)   // 2080 lower-tri entries

// ---- shared memory layout (floats) ----
#define O_W1  0
#define O_W2  (O_W1 + L_N*H_N)        // 16384
#define O_B1  (O_W2 + H_N*L_N)        // +16384
#define O_B2  (O_B1 + H_N)
#define O_Z   (O_B2 + L_N)
#define O_HID (O_Z + S_N*L_N)
#define O_M   (O_HID + S_N*H_N)
#define O_A   (O_M + S_N*L_N)
#define O_BI  (O_A + L_N*LP)
#define O_JP  (O_BI + L_N*LP)
#define O_KT  (O_JP + L_N*LP)
#define O_WT  (O_KT + L_N*R_N)
#define O_MP  (O_WT + S_N*L_N)
#define O_HF  (O_MP + L_N)
#define O_MF  (O_HF + L_N)
#define O_U   (O_MF + L_N)
#define O_DG  (O_U + L_N)
#define O_QD  (O_DG + L_N)
#define O_J0  (O_QD + L_N)
#define O_M0  (O_J0 + L_N)
#define O_SP  (O_M0 + L_N)
#define SMF   (O_SP + L_N)            // total floats (= 54336 -> 217344 bytes)

// ---- output offsets (tuple flattened in order) ----
#define OFF_ZF 0LL
#define OFF_MFo ((long long)S_N*B_N*T_N*L_N)                  // 26,214,400
#define OFF_MPo (OFF_MFo + (long long)B_N*T_N*L_N)            // +1,638,400
#define OFF_PF  (OFF_MPo + (long long)B_N*T_N*L_N)
#define OFF_PP  (OFF_PF + (long long)B_N*T_N*L_N*L_N)

// map linear index e -> (i,j) with j<=i over the lower triangle
__device__ __forceinline__ void trimap(int e, int &i, int &j) {
    int ii = (int)((sqrtf(8.0f*(float)e + 1.0f) - 1.0f) * 0.5f);
    while ((ii+1)*(ii+2)/2 <= e) ++ii;
    while (ii*(ii+1)/2 > e) --ii;
    i = ii;
    j = e - ii*(ii+1)/2;
}

// In-place Cholesky of lower-triangular-stored A (stride LP).
// One barrier per column (LDL-style rank-1 updates with unscaled columns),
// then one parallel scaling pass. dg[j] = 1/L[j][j] on exit (needed by solver).
__device__ void chol_inplace(float* A, float* dg, int tid) {
    const int warp = tid >> 5, lane = tid & 31;
    #pragma unroll 1
    for (int j = 0; j < L_N - 1; ++j) {
        __syncthreads();
        const float inv = 1.0f / A[j*LP + j];
        #pragma unroll 1
        for (int i = j + 1 + warp; i < L_N; i += NT/32) {
            const float fac = A[i*LP + j] * inv;
            for (int kk = j + 1 + lane; kk <= i; kk += 32)
                A[i*LP + kk] -= fac * A[kk*LP + j];
        }
    }
    __syncthreads();
    if (tid < L_N) dg[tid] = rsqrtf(A[tid*LP + tid]);
    __syncthreads();
    for (int e = tid; e < TRI; e += NT) {
        int i, j; trimap(e, i, j);
        A[i*LP + j] *= dg[j];     // diag becomes sqrt(d_j); dg[j] stays = 1/L[j][j]
    }
    __syncthreads();
}

// X = inv(A) for lower-triangular A (reads lower part only, writes lower part of X).
// Row-sweep forward substitution, all 64 unit-vector RHS in parallel:
// 4 lanes per column split the dot product, shfl-reduced.
__device__ void tri_inverse(const float* A, float* X, const float* dg, int tid) {
    const int c = tid >> 2, r = tid & 3;
    #pragma unroll 1
    for (int i = 0; i < L_N; ++i) {
        __syncthreads();
        float sum = 0.0f;
        for (int j = c + r; j < i; j += 4)
            sum += A[i*LP + j] * X[j*LP + c];
        sum += __shfl_down_sync(0xffffffffu, sum, 1);
        sum += __shfl_down_sync(0xffffffffu, sum, 2);
        if (r == 0 && c <= i)
            X[i*LP + c] = (c == i) ? dg[i] : (-sum * dg[i]);
    }
    __syncthreads();
}

__global__ void __launch_bounds__(NT, 1)
nlf_kernel(const float* __restrict__ gk,  const float* __restrict__ gK,
           const float* __restrict__ glogQ, const float* __restrict__ gm0,
           const float* __restrict__ glogv0, const float* __restrict__ gW1,
           const float* __restrict__ gb1, const float* __restrict__ gW2,
           const float* __restrict__ gb2, const float* __restrict__ gw,
           float* __restrict__ out)
{
    extern __shared__ float sm[];
    const int tid = threadIdx.x;
    const int b   = blockIdx.x;

    // ---- one-time setup: weights + softplus-derived vectors ----
    {
        const float4* g1 = (const float4*)gW1;
        float4* s1 = (float4*)(sm + O_W1);
        for (int i = tid; i < L_N*H_N/4; i += NT) s1[i] = g1[i];
        const float4* g2 = (const float4*)gW2;
        float4* s2 = (float4*)(sm + O_W2);
        for (int i = tid; i < H_N*L_N/4; i += NT) s2[i] = g2[i];
        if (tid < H_N) sm[O_B1 + tid] = gb1[tid];
        if (tid < L_N) {
            sm[O_B2 + tid] = gb2[tid];
            float q = glogQ[tid], v = glogv0[tid];
            float qd = fmaxf(q, 0.f) + log1pf(expf(-fabsf(q)));   // softplus(log_Q)
            float p0 = fmaxf(v, 0.f) + log1pf(expf(-fabsf(v)));   // softplus(log_v0)
            sm[O_QD + tid] = qd;
            sm[O_J0 + tid] = 1.0f / p0;
            sm[O_SP + tid] = sqrtf(p0);
            sm[O_M0 + tid] = gm0[tid];
        }
    }
    __syncthreads();

    float* const sZ  = sm + O_Z;
    float* const sHID= sm + O_HID;
    float* const sM  = sm + O_M;
    float* const sA  = sm + O_A;
    float* const sBI = sm + O_BI;
    float* const sJP = sm + O_JP;
    float* const sKT = sm + O_KT;
    float* const sWT = sm + O_WT;
    float* const sMP = sm + O_MP;
    float* const sHF = sm + O_HF;
    float* const sMF = sm + O_MF;
    float* const sU  = sm + O_U;
    float* const sDG = sm + O_DG;

    #pragma unroll 1
    for (int t = 0; t < T_N; ++t) {
        // ---- stage K_t (64x16) and w_t (16x64) early (prefetch-ish) ----
        {
            const float4* gkt = (const float4*)(gK + ((long long)(b*T_N + t))*L_N*R_N);
            float4* s4 = (float4*)sKT;
            for (int i = tid; i < L_N*R_N/4; i += NT) s4[i] = gkt[i];
            // w[t][s][b][:]: per-sample rows are strided by B*L floats
            const int ss = tid >> 4;            // 16 samples
            const int l4 = (tid & 15) * 4;      // 16 float4 per sample row
            const float4 wv = *(const float4*)(gw + (((long long)t*S_N + ss)*B_N + b)*L_N + l4);
            *(float4*)(sWT + ss*L_N + l4) = wv;
        }
        __syncthreads();

        if (t == 0) {
            if (tid < L_N) {
                sMP[tid] = sm[O_M0 + tid];
                sHF[tid] = sm[O_J0 + tid]*sm[O_M0 + tid] + gk[((long long)(b*T_N))*L_N + tid];
            }
            // P_p_chol[t=0] = diag(sqrt(P0))
            {
                float* po = out + OFF_PP + ((long long)(b*T_N + t))*L_N*L_N;
                for (int e = tid; e < L_N*L_N; e += NT) {
                    int i = e >> 6, j = e & 63;
                    po[e] = (i == j) ? sm[O_SP + i] : 0.0f;
                }
            }
            // J_f = diag(J0) + K0 K0^T (lower only)
            for (int e = tid; e < TRI; e += NT) {
                int i, j; trimap(e, i, j);
                float s = 0.f;
                #pragma unroll
                for (int rr = 0; rr < R_N; rr += 4) {
                    float4 a  = *(const float4*)(sKT + i*R_N + rr);
                    float4 bb = *(const float4*)(sKT + j*R_N + rr);
                    s += a.x*bb.x + a.y*bb.y + a.z*bb.z + a.w*bb.w;
                }
                if (i == j) s += sm[O_J0 + i];
                sA[i*LP + j] = s;
            }
        } else {
            // ---- MLP layer 1: hid = tanh(z @ W1 + b1), one h per thread ----
            {
                const int h = tid;
                float acc[S_N];
                const float bb1 = sm[O_B1 + h];
                #pragma unroll
                for (int s = 0; s < S_N; ++s) acc[s] = bb1;
                #pragma unroll 4
                for (int l = 0; l < L_N; l += 4) {
                    const float w0 = sm[O_W1 + (l+0)*H_N + h];
                    const float w1 = sm[O_W1 + (l+1)*H_N + h];
                    const float w2 = sm[O_W1 + (l+2)*H_N + h];
                    const float w3 = sm[O_W1 + (l+3)*H_N + h];
                    #pragma unroll
                    for (int s = 0; s < S_N; ++s) {
                        float4 z4 = *(const float4*)(sZ + s*L_N + l);
                        acc[s] += z4.x*w0 + z4.y*w1 + z4.z*w2 + z4.w*w3;
                    }
                }
                #pragma unroll
                for (int s = 0; s < S_N; ++s) sHID[s*H_N + h] = tanhf(acc[s]);
            }
            __syncthreads();
            // ---- MLP layer 2: m = hid @ W2 + b2, (4 samples, 1 column) per thread ----
            {
                const int lo = tid & 63;
                const int s0 = (tid >> 6) * 4;
                const float bb2 = sm[O_B2 + lo];
                float a0 = bb2, a1 = bb2, a2 = bb2, a3 = bb2;
                #pragma unroll 4
                for (int h = 0; h < H_N; h += 4) {
                    const float w0 = sm[O_W2 + (h+0)*L_N + lo];
                    const float w1 = sm[O_W2 + (h+1)*L_N + lo];
                    const float w2 = sm[O_W2 + (h+2)*L_N + lo];
                    const float w3 = sm[O_W2 + (h+3)*L_N + lo];
                    float4 h0 = *(const float4*)(sHID + (s0+0)*H_N + h);
                    float4 h1 = *(const float4*)(sHID + (s0+1)*H_N + h);
                    float4 h2 = *(const float4*)(sHID + (s0+2)*H_N + h);
                    float4 h3 = *(const float4*)(sHID + (s0+3)*H_N + h);
                    a0 += h0.x*w0 + h0.y*w1 + h0.z*w2 + h0.w*w3;
                    a1 += h1.x*w0 + h1.y*w1 + h1.z*w2 + h1.w*w3;
                    a2 += h2.x*w0 + h2.y*w1 + h2.z*w2 + h2.w*w3;
                    a3 += h3.x*w0 + h3.y*w1 + h3.z*w2 + h3.w*w3;
                }
                sM[(s0+0)*L_N + lo] = a0;
                sM[(s0+1)*L_N + lo] = a1;
                sM[(s0+2)*L_N + lo] = a2;
                sM[(s0+3)*L_N + lo] = a3;
            }
            __syncthreads();
            // ---- m_p = mean_s m ----
            if (tid < L_N) {
                float s = 0.f;
                #pragma unroll
                for (int ss = 0; ss < S_N; ++ss) s += sM[ss*L_N + tid];
                sMP[tid] = s * (1.0f/S_N);
            }
            __syncthreads();
            // ---- P_p = diag(Q) + Ezz/S - m_p m_p^T (lower only) ----
            for (int e = tid; e < TRI; e += NT) {
                int i, j; trimap(e, i, j);
                float s = 0.f;
                #pragma unroll
                for (int ss = 0; ss < S_N; ++ss) s += sM[ss*L_N + i]*sM[ss*L_N + j];
                float v = s * (1.0f/S_N) - sMP[i]*sMP[j];
                if (i == j) v += sm[O_QD + i];
                sA[i*LP + j] = v;
            }
            chol_inplace(sA, sDG, tid);          // sA = Lp
            // write P_p_chol
            {
                float* po = out + OFF_PP + ((long long)(b*T_N + t))*L_N*L_N;
                for (int e = tid; e < L_N*L_N; e += NT) {
                    int i = e >> 6, j = e & 63;
                    po[e] = (j <= i) ? sA[i*LP + j] : 0.0f;
                }
            }
            tri_inverse(sA, sBI, sDG, tid);      // sBI = Lp^{-1}
            // ---- J_p = BI^T BI (lower + mirror) ----
            for (int e = tid; e < TRI; e += NT) {
                int i, j; trimap(e, i, j);       // i >= j; sum k = i..63
                float s0 = 0.f, s1 = 0.f;
                int kk = i;
                for (; kk + 1 < L_N; kk += 2) {
                    s0 += sBI[(kk+0)*LP + i] * sBI[(kk+0)*LP + j];
                    s1 += sBI[(kk+1)*LP + i] * sBI[(kk+1)*LP + j];
                }
                if (kk < L_N) s0 += sBI[kk*LP + i] * sBI[kk*LP + j];
                const float s = s0 + s1;
                sJP[i*LP + j] = s;
                sJP[j*LP + i] = s;
            }
            __syncthreads();
            // ---- h_f = J_p m_p + k_t ----
            if (tid < L_N) {
                const float* row = sJP + tid*LP;
                float s0=0,s1=0,s2=0,s3=0;
                #pragma unroll
                for (int j = 0; j < L_N; j += 4) {
                    s0 += row[j+0]*sMP[j+0];
                    s1 += row[j+1]*sMP[j+1];
                    s2 += row[j+2]*sMP[j+2];
                    s3 += row[j+3]*sMP[j+3];
                }
                sHF[tid] = (s0+s1)+(s2+s3) + gk[((long long)(b*T_N + t))*L_N + tid];
            }
            __syncthreads();
            // ---- J_f = J_p + K_t K_t^T (lower only) ----
            for (int e = tid; e < TRI; e += NT) {
                int i, j; trimap(e, i, j);
                float s = 0.f;
                #pragma unroll
                for (int rr = 0; rr < R_N; rr += 4) {
                    float4 a  = *(const float4*)(sKT + i*R_N + rr);
                    float4 bb = *(const float4*)(sKT + j*R_N + rr);
                    s += a.x*bb.x + a.y*bb.y + a.z*bb.z + a.w*bb.w;
                }
                sA[i*LP + j] = sJP[i*LP + j] + s;
            }
        }

        // ================= common tail =================
        chol_inplace(sA, sDG, tid);        // sA = Lf (internal leading barrier orders the build)
        tri_inverse(sA, sBI, sDG, tid);    // sBI = Lf^{-1}

        // m_f = Lf^{-T} (Lf^{-1} h_f)
        if (tid < L_N) {
            const int i = tid;
            float s0 = 0.f, s1 = 0.f;
            int j = 0;
            for (; j + 1 <= i; j += 2) {
                s0 += sBI[i*LP + j]   * sHF[j];
                s1 += sBI[i*LP + j+1] * sHF[j+1];
            }
            if (j <= i) s0 += sBI[i*LP + j] * sHF[j];
            sU[i] = s0 + s1;
        }
        __syncthreads();
        if (tid < L_N) {
            const int i = tid;
            float s0 = 0.f, s1 = 0.f;
            int kk = i;
            for (; kk + 1 < L_N; kk += 2) {
                s0 += sBI[(kk+0)*LP + i] * sU[kk+0];
                s1 += sBI[(kk+1)*LP + i] * sU[kk+1];
            }
            if (kk < L_N) s0 += sBI[kk*LP + i] * sU[kk];
            sMF[i] = s0 + s1;
            out[OFF_MPo + ((long long)(b*T_N + t))*L_N + i] = sMP[i];
        }
        __syncthreads();
        if (tid < L_N)
            out[OFF_MFo + ((long long)(b*T_N + t))*L_N + tid] = sMF[tid];
        // P_f_chol = (Lf^{-1})^T  (upper triangular, zeros below)
        {
            float* po = out + OFF_PF + ((long long)(b*T_N + t))*L_N*L_N;
            for (int e = tid; e < L_N*L_N; e += NT) {
                int i = e >> 6, j = e & 63;
                po[e] = (j >= i) ? sBI[j*LP + i] : 0.0f;
            }
        }
        // z_f[s] = m_f + Pf_chol @ w_t[s]  (sum over j >= i of BI[j][i] * w[s][j])
        {
            const int i  = tid & 63;
            const int s0 = (tid >> 6) * 4;
            float z0 = sMF[i], z1 = z0, z2 = z0, z3 = z0;
            for (int j = i; j < L_N; ++j) {
                const float bv = sBI[j*LP + i];
                z0 += bv * sWT[(s0+0)*L_N + j];
                z1 += bv * sWT[(s0+1)*L_N + j];
                z2 += bv * sWT[(s0+2)*L_N + j];
                z3 += bv * sWT[(s0+3)*L_N + j];
            }
            sZ[(s0+0)*L_N + i] = z0;
            sZ[(s0+1)*L_N + i] = z1;
            sZ[(s0+2)*L_N + i] = z2;
            sZ[(s0+3)*L_N + i] = z3;
            out[((((long long)(s0+0))*B_N + b)*T_N + t)*L_N + i] = z0;
            out[((((long long)(s0+1))*B_N + b)*T_N + t)*L_N + i] = z1;
            out[((((long long)(s0+2))*B_N + b)*T_N + t)*L_N + i] = z2;
            out[((((long long)(s0+3))*B_N + b)*T_N + t)*L_N + i] = z3;
        }
        __syncthreads();   // sZ ready for next step's MLP; staging buffers free
    }
}

extern "C" void kernel_launch(void* const* d_in, const int* in_sizes, int n_in,
                              void* d_out, int out_size) {
    const float* gk     = (const float*)d_in[0];
    const float* gK     = (const float*)d_in[1];
    const float* glogQ  = (const float*)d_in[2];
    const float* gm0    = (const float*)d_in[3];
    const float* glogv0 = (const float*)d_in[4];
    const float* gW1    = (const float*)d_in[5];
    const float* gb1    = (const float*)d_in[6];
    const float* gW2    = (const float*)d_in[7];
    const float* gb2    = (const float*)d_in[8];
    const float* gw     = (const float*)d_in[9];
    float* out = (float*)d_out;

    const size_t smem = (size_t)SMF * sizeof(float);   // 217,344 bytes
    cudaFuncSetAttribute(nlf_kernel, cudaFuncAttributeMaxDynamicSharedMemorySize, (int)smem);
    nlf_kernel<<<B_N, NT, smem>>>(gk, gK, glogQ, gm0, glogv0, gW1, gb1, gW2, gb2, gw, out);
}

// round 5
// speedup vs baseline: 1.7545x; 1.7545x over previous
#include <cuda_runtime.h>
#include <math.h>

// Problem constants
#define S_N 16
#define B_N 128
#define T_N 200
#define L_N 64
#define R_N 16
#define H_N 256
#define NT  256
#define LP  68            // row stride: 68%4==0 -> every row 16B-aligned; col stride 68%32=4 banks
#define MTS 20            // transposed-m row stride (aligned, bank-spread)
#define TRIN 2080

// ---- shared memory layout (float offsets) ----
#define O_W1  0
#define O_W2  (O_W1 + L_N*H_N)
#define O_B1  (O_W2 + H_N*L_N)
#define O_B2  (O_B1 + H_N)
#define O_Z   (O_B2 + L_N)
#define O_SCR (O_Z + S_N*L_N)         // 4096: MLP hidden, later G-block scratch (1536)
#define O_MT  (O_SCR + S_N*H_N)       // m transposed [l][s], stride MTS
#define O_A   (O_MT + L_N*MTS)
#define O_BI  (O_A + L_N*LP)
#define O_KT  (O_BI + L_N*LP)
#define O_WT  (O_KT + L_N*R_N)
#define O_MP  (O_WT + S_N*L_N)
#define O_HF  (O_MP + L_N)
#define O_MF  (O_HF + L_N)
#define O_U   (O_MF + L_N)
#define O_KV  (O_U + L_N)
#define O_QD  (O_KV + L_N)
#define O_J0  (O_QD + L_N)
#define O_M0  (O_J0 + L_N)
#define O_SP  (O_M0 + L_N)
#define FLOAT_END (O_SP + L_N)
// index tables (bytes)
#define BYTE_T64 (FLOAT_END*4)
#define BYTE_T48 (BYTE_T64 + TRIN*2)
#define BYTE_T32 (BYTE_T48 + 1176*2)
#define BYTE_T16 (BYTE_T32 + 528*2)
#define SMEM_BYTES (BYTE_T16 + 136*2)

// ---- output offsets (tuple flattened in order) ----
#define OFF_ZF 0LL
#define OFF_MFo ((long long)S_N*B_N*T_N*L_N)
#define OFF_MPo (OFF_MFo + (long long)B_N*T_N*L_N)
#define OFF_PF  (OFF_MPo + (long long)B_N*T_N*L_N)
#define OFF_PP  (OFF_PF + (long long)B_N*T_N*L_N*L_N)

__device__ __forceinline__ void trimap(int e, int &i, int &j) {
    int ii = (int)((sqrtf(8.0f*(float)e + 1.0f) - 1.0f) * 0.5f);
    while ((ii+1)*(ii+2)/2 <= e) ++ii;
    while (ii*(ii+1)/2 > e) --ii;
    i = ii;
    j = e - ii*(ii+1)/2;
}

__device__ __forceinline__ float dot4(float4 a, float4 b) {
    return a.x*b.x + a.y*b.y + a.z*b.z + a.w*b.w;
}

// ---- warp-level 16x16 Cholesky + inverse (warp 0 only, rows in lanes) ----
// Ad: diag block base (stride LP). Writes L (lower) back into Ad.
// Xd: writes invL (lower, zeros above diagonal) into Xd.
__device__ __forceinline__ void warp_diag(float* Ad, float* Xd, int lane) {
    const int r = lane & 15;
    float a[16];
    #pragma unroll
    for (int k = 0; k < 16; ++k) a[k] = Ad[r*LP + k];
    float mydiag = 1.0f;
    #pragma unroll
    for (int c = 0; c < 16; ++c) {
        float dc = __shfl_sync(0xffffffffu, a[c], c);
        float rd = rsqrtf(dc);
        if (r >= c) a[c] *= rd;
        if (r == c) mydiag = a[c];
        #pragma unroll
        for (int k = c + 1; k < 16; ++k) {
            float lkc = __shfl_sync(0xffffffffu, a[c], k);
            if (r >= k) a[k] -= a[c] * lkc;
        }
    }
    const float invd = 1.0f / mydiag;
    if (lane < 16) {
        #pragma unroll
        for (int k = 0; k < 16; ++k)
            if (k <= r) Ad[r*LP + k] = a[k];
    }
    // inversion: lane c(=r) computes column c of X = invL
    float x[16];
    #pragma unroll
    for (int k = 0; k < 16; ++k) x[k] = 0.0f;
    #pragma unroll
    for (int rr = 0; rr < 16; ++rr) {
        float s = 0.0f;
        #pragma unroll
        for (int j = 0; j < 16; ++j) {
            if (j < rr) {
                float Lrj = __shfl_sync(0xffffffffu, a[j], rr);
                s += Lrj * x[j];
            }
        }
        float di = __shfl_sync(0xffffffffu, invd, rr);
        float v = ((r == rr ? 1.0f : 0.0f) - s) * di;
        x[rr] = (r <= rr) ? v : 0.0f;
    }
    if (lane < 16) {
        #pragma unroll
        for (int rr = 0; rr < 16; ++rr) Xd[rr*LP + r] = x[rr];
    }
}

// ---- blocked 64x64 Cholesky: sA -> L (lower), sBI diag blocks -> invL_JJ ----
__device__ __noinline__ void chol64(float* sA, float* sBI,
                                    const uchar2* T48, const uchar2* T32, const uchar2* T16,
                                    int tid) {
    const int lane = tid & 31;
    const int warp = tid >> 5;
    #pragma unroll 1
    for (int J = 0; J < 4; ++J) {
        if (warp == 0) warp_diag(sA + 16*J*(LP+1), sBI + 16*J*(LP+1), lane);
        __syncthreads();
        if (J == 3) break;
        const int base = 16*(J+1);
        const int n = (64 - base) * 16;
        // panel: L[i][c] = sum_k A[i][k+16J] * invL_JJ[c][k]   (compute to regs, then write)
        float pv[3];
        {
            int p = 0;
            #pragma unroll 1
            for (int e = tid; e < n; e += NT, ++p) {
                const int i = base + (e >> 4), c = e & 15;
                const float4* Ar = (const float4*)(sA + i*LP + 16*J);
                const float4* Xr = (const float4*)(sBI + (16*J + c)*LP + 16*J);
                pv[p] = dot4(Ar[0], Xr[0]) + dot4(Ar[1], Xr[1])
                      + dot4(Ar[2], Xr[2]) + dot4(Ar[3], Xr[3]);
            }
        }
        __syncthreads();
        {
            int p = 0;
            #pragma unroll 1
            for (int e = tid; e < n; e += NT, ++p) {
                const int i = base + (e >> 4), c = e & 15;
                sA[i*LP + 16*J + c] = pv[p];
            }
        }
        __syncthreads();
        // trailing update: A[i][j] -= sum_k L[i][k]L[j][k] over block-J columns
        const uchar2* TT = (J == 0) ? T48 : (J == 1) ? T32 : T16;
        const int nt = (J == 0) ? 1176 : (J == 1) ? 528 : 136;
        #pragma unroll 1
        for (int e = tid; e < nt; e += NT) {
            const uchar2 lj = TT[e];
            const int i = base + lj.x, j = base + lj.y;
            const float4* Li = (const float4*)(sA + i*LP + 16*J);
            const float4* Lj = (const float4*)(sA + j*LP + 16*J);
            float acc = sA[i*LP + j];
            acc -= dot4(Li[0], Lj[0]) + dot4(Li[1], Lj[1])
                 + dot4(Li[2], Lj[2]) + dot4(Li[3], Lj[3]);
            sA[i*LP + j] = acc;
        }
        __syncthreads();
    }
}

// ---- blocked triangular inverse: sBI <- inv(L) (lower, zeros in diag-block uppers)
// Requires: sA = L (from chol64), sBI diag blocks = invL_JJ. G: 1536-float scratch.
__device__ __noinline__ void triinv64(const float* sA, float* sBI, float* G, int tid) {
    // G[I][K] = invL_II * L[I][K]  (6 blocks)
    #pragma unroll 1
    for (int e = tid; e < 1536; e += NT) {
        const int blk = e >> 8, p = (e >> 4) & 15, q = e & 15;
        int I, K;
        if      (blk == 0) { I = 1; K = 0; }
        else if (blk == 1) { I = 2; K = 0; }
        else if (blk == 2) { I = 2; K = 1; }
        else if (blk == 3) { I = 3; K = 0; }
        else if (blk == 4) { I = 3; K = 1; }
        else               { I = 3; K = 2; }
        const float4* xr = (const float4*)(sBI + (16*I + p)*LP + 16*I);
        float gv[16];
        *(float4*)(gv+0)  = xr[0]; *(float4*)(gv+4)  = xr[1];
        *(float4*)(gv+8)  = xr[2]; *(float4*)(gv+12) = xr[3];
        const float* Lc = sA + 16*I*LP + 16*K + q;
        float s = 0.0f;
        #pragma unroll
        for (int r = 0; r < 16; ++r) s += gv[r] * Lc[r*LP];
        G[blk*256 + p*16 + q] = s;
    }
    __syncthreads();
    // phase 1: X[I][I-1] = -G[I][I-1] * X[I-1][I-1]
    #pragma unroll 1
    for (int e = tid; e < 768; e += NT) {
        const int b = e >> 8, p = (e >> 4) & 15, q = e & 15;
        const int I = b + 1, Jb = b;
        const int gi = I*(I-1)/2 + (I-1);
        const float* g = G + gi*256 + p*16;
        float gv[16];
        *(float4*)(gv+0)  = *(const float4*)(g+0);  *(float4*)(gv+4)  = *(const float4*)(g+4);
        *(float4*)(gv+8)  = *(const float4*)(g+8);  *(float4*)(gv+12) = *(const float4*)(g+12);
        const float* xc = sBI + (16*Jb)*LP + 16*Jb + q;
        float s = 0.0f;
        #pragma unroll
        for (int k = 0; k < 16; ++k) s += gv[k] * xc[k*LP];
        sBI[(16*I + p)*LP + 16*Jb + q] = -s;
    }
    __syncthreads();
    // phase 2: X[2][0], X[3][1]
    #pragma unroll 1
    for (int e = tid; e < 512; e += NT) {
        const int b = e >> 8, p = (e >> 4) & 15, q = e & 15;
        const int I = (b == 0) ? 2 : 3, Jb = (b == 0) ? 0 : 1;
        float s = 0.0f;
        #pragma unroll
        for (int K = 0; K < 2; ++K) {
            const int Kb = Jb + K;
            const float* g = G + (I*(I-1)/2 + Kb)*256 + p*16;
            float gv[16];
            *(float4*)(gv+0)  = *(const float4*)(g+0);  *(float4*)(gv+4)  = *(const float4*)(g+4);
            *(float4*)(gv+8)  = *(const float4*)(g+8);  *(float4*)(gv+12) = *(const float4*)(g+12);
            const float* xc = sBI + (16*Kb)*LP + 16*Jb + q;
            #pragma unroll
            for (int k = 0; k < 16; ++k) s += gv[k] * xc[k*LP];
        }
        sBI[(16*I + p)*LP + 16*Jb + q] = -s;
    }
    __syncthreads();
    // phase 3: X[3][0]
    #pragma unroll 1
    for (int e = tid; e < 256; e += NT) {
        const int p = (e >> 4) & 15, q = e & 15;
        float s = 0.0f;
        #pragma unroll
        for (int Kb = 0; Kb < 3; ++Kb) {
            const float* g = G + (3 + Kb)*256 + p*16;   // gidx(3,K)=3+K
            float gv[16];
            *(float4*)(gv+0)  = *(const float4*)(g+0);  *(float4*)(gv+4)  = *(const float4*)(g+4);
            *(float4*)(gv+8)  = *(const float4*)(g+8);  *(float4*)(gv+12) = *(const float4*)(g+12);
            const float* xc = sBI + (16*Kb)*LP + 0 + q;
            #pragma unroll
            for (int k = 0; k < 16; ++k) s += gv[k] * xc[k*LP];
        }
        sBI[(48 + p)*LP + q] = -s;
    }
    __syncthreads();
}

__global__ void __launch_bounds__(NT, 1)
nlf_kernel(const float* __restrict__ gk,  const float* __restrict__ gK,
           const float* __restrict__ glogQ, const float* __restrict__ gm0,
           const float* __restrict__ glogv0, const float* __restrict__ gW1,
           const float* __restrict__ gb1, const float* __restrict__ gW2,
           const float* __restrict__ gb2, const float* __restrict__ gw,
           float* __restrict__ out)
{
    extern __shared__ float sm[];
    const int tid = threadIdx.x;
    const int b   = blockIdx.x;

    uchar2* const T64 = (uchar2*)((char*)sm + BYTE_T64);
    uchar2* const T48 = (uchar2*)((char*)sm + BYTE_T48);
    uchar2* const T32 = (uchar2*)((char*)sm + BYTE_T32);
    uchar2* const T16 = (uchar2*)((char*)sm + BYTE_T16);

    // ---- one-time setup ----
    {
        const float4* g1 = (const float4*)gW1;
        float4* s1 = (float4*)(sm + O_W1);
        for (int i = tid; i < L_N*H_N/4; i += NT) s1[i] = g1[i];
        const float4* g2 = (const float4*)gW2;
        float4* s2 = (float4*)(sm + O_W2);
        for (int i = tid; i < H_N*L_N/4; i += NT) s2[i] = g2[i];
        if (tid < H_N) sm[O_B1 + tid] = gb1[tid];
        if (tid < L_N) {
            sm[O_B2 + tid] = gb2[tid];
            float q = glogQ[tid], v = glogv0[tid];
            float qd = fmaxf(q, 0.f) + log1pf(expf(-fabsf(q)));
            float p0 = fmaxf(v, 0.f) + log1pf(expf(-fabsf(v)));
            sm[O_QD + tid] = qd;
            sm[O_J0 + tid] = 1.0f / p0;
            sm[O_SP + tid] = sqrtf(p0);
            sm[O_M0 + tid] = gm0[tid];
        }
        for (int e = tid; e < TRIN; e += NT) { int i, j; trimap(e, i, j); T64[e] = make_uchar2((unsigned char)i, (unsigned char)j); }
        for (int e = tid; e < 1176; e += NT) { int i, j; trimap(e, i, j); T48[e] = make_uchar2((unsigned char)i, (unsigned char)j); }
        for (int e = tid; e < 528;  e += NT) { int i, j; trimap(e, i, j); T32[e] = make_uchar2((unsigned char)i, (unsigned char)j); }
        for (int e = tid; e < 136;  e += NT) { int i, j; trimap(e, i, j); T16[e] = make_uchar2((unsigned char)i, (unsigned char)j); }
    }
    __syncthreads();

    float* const sZ   = sm + O_Z;
    float* const sHID = sm + O_SCR;
    float* const sG   = sm + O_SCR;
    float* const sMT  = sm + O_MT;
    float* const sA   = sm + O_A;
    float* const sBI  = sm + O_BI;
    float* const sKT  = sm + O_KT;
    float* const sWT  = sm + O_WT;
    float* const sMP  = sm + O_MP;
    float* const sHF  = sm + O_HF;
    float* const sMF  = sm + O_MF;
    float* const sU   = sm + O_U;
    float* const sKV  = sm + O_KV;

    #pragma unroll 1
    for (int t = 0; t < T_N; ++t) {
        // ---- stage K_t, w_t, k_t ----
        {
            const float4* gkt = (const float4*)(gK + ((long long)(b*T_N + t))*L_N*R_N);
            float4* s4 = (float4*)sKT;
            for (int i = tid; i < L_N*R_N/4; i += NT) s4[i] = gkt[i];
            const int ss = tid >> 4;
            const int l4 = (tid & 15) * 4;
            const float4 wv = *(const float4*)(gw + (((long long)t*S_N + ss)*B_N + b)*L_N + l4);
            *(float4*)(sWT + ss*L_N + l4) = wv;
            if (tid < L_N) sKV[tid] = gk[((long long)(b*T_N + t))*L_N + tid];
        }
        __syncthreads();

        if (t == 0) {
            if (tid < L_N) {
                sMP[tid] = sm[O_M0 + tid];
                sHF[tid] = sm[O_J0 + tid]*sm[O_M0 + tid] + sKV[tid];
            }
            // P_p_chol[0] = diag(sqrt(P0))
            {
                float4* po4 = (float4*)(out + OFF_PP + ((long long)(b*T_N + t))*L_N*L_N);
                for (int f = tid; f < 1024; f += NT) {
                    const int i = f >> 4, j0 = (f & 15) * 4;
                    float4 v;
                    v.x = (j0+0 == i) ? sm[O_SP + i] : 0.0f;
                    v.y = (j0+1 == i) ? sm[O_SP + i] : 0.0f;
                    v.z = (j0+2 == i) ? sm[O_SP + i] : 0.0f;
                    v.w = (j0+3 == i) ? sm[O_SP + i] : 0.0f;
                    po4[f] = v;
                }
            }
            // J_f = diag(J0) + K0 K0^T
            for (int e = tid; e < TRIN; e += NT) {
                const uchar2 ij = T64[e];
                const int i = ij.x, j = ij.y;
                const float4* ki = (const float4*)(sKT + i*R_N);
                const float4* kj = (const float4*)(sKT + j*R_N);
                float s = dot4(ki[0], kj[0]) + dot4(ki[1], kj[1])
                        + dot4(ki[2], kj[2]) + dot4(ki[3], kj[3]);
                if (i == j) s += sm[O_J0 + i];
                sA[i*LP + j] = s;
            }
            __syncthreads();
        } else {
            // ---- MLP layer 1 ----
            {
                const int h = tid;
                float acc[S_N];
                const float bb1 = sm[O_B1 + h];
                #pragma unroll
                for (int s = 0; s < S_N; ++s) acc[s] = bb1;
                #pragma unroll 4
                for (int l = 0; l < L_N; l += 4) {
                    const float w0 = sm[O_W1 + (l+0)*H_N + h];
                    const float w1 = sm[O_W1 + (l+1)*H_N + h];
                    const float w2 = sm[O_W1 + (l+2)*H_N + h];
                    const float w3 = sm[O_W1 + (l+3)*H_N + h];
                    #pragma unroll
                    for (int s = 0; s < S_N; ++s) {
                        float4 z4 = *(const float4*)(sZ + s*L_N + l);
                        acc[s] += z4.x*w0 + z4.y*w1 + z4.z*w2 + z4.w*w3;
                    }
                }
                #pragma unroll
                for (int s = 0; s < S_N; ++s) sHID[s*H_N + h] = tanhf(acc[s]);
            }
            __syncthreads();
            // ---- MLP layer 2 -> sMT transposed [l][s] ----
            {
                const int lo = tid & 63;
                const int s0 = (tid >> 6) * 4;
                const float bb2 = sm[O_B2 + lo];
                float a0 = bb2, a1 = bb2, a2 = bb2, a3 = bb2;
                #pragma unroll 4
                for (int h = 0; h < H_N; h += 4) {
                    const float w0 = sm[O_W2 + (h+0)*L_N + lo];
                    const float w1 = sm[O_W2 + (h+1)*L_N + lo];
                    const float w2 = sm[O_W2 + (h+2)*L_N + lo];
                    const float w3 = sm[O_W2 + (h+3)*L_N + lo];
                    float4 h0 = *(const float4*)(sHID + (s0+0)*H_N + h);
                    float4 h1 = *(const float4*)(sHID + (s0+1)*H_N + h);
                    float4 h2 = *(const float4*)(sHID + (s0+2)*H_N + h);
                    float4 h3 = *(const float4*)(sHID + (s0+3)*H_N + h);
                    a0 += h0.x*w0 + h0.y*w1 + h0.z*w2 + h0.w*w3;
                    a1 += h1.x*w0 + h1.y*w1 + h1.z*w2 + h1.w*w3;
                    a2 += h2.x*w0 + h2.y*w1 + h2.z*w2 + h2.w*w3;
                    a3 += h3.x*w0 + h3.y*w1 + h3.z*w2 + h3.w*w3;
                }
                *(float4*)(sMT + lo*MTS + s0) = make_float4(a0, a1, a2, a3);
            }
            __syncthreads();
            // ---- m_p ----
            if (tid < L_N) {
                const float4* mr = (const float4*)(sMT + tid*MTS);
                float4 m0v = mr[0], m1v = mr[1], m2v = mr[2], m3v = mr[3];
                sMP[tid] = (m0v.x+m0v.y+m0v.z+m0v.w + m1v.x+m1v.y+m1v.z+m1v.w
                          + m2v.x+m2v.y+m2v.z+m2v.w + m3v.x+m3v.y+m3v.z+m3v.w) * (1.0f/S_N);
            }
            __syncthreads();
            // ---- P_p build ----
            for (int e = tid; e < TRIN; e += NT) {
                const uchar2 ij = T64[e];
                const int i = ij.x, j = ij.y;
                const float4* mi = (const float4*)(sMT + i*MTS);
                const float4* mj = (const float4*)(sMT + j*MTS);
                float s = dot4(mi[0], mj[0]) + dot4(mi[1], mj[1])
                        + dot4(mi[2], mj[2]) + dot4(mi[3], mj[3]);
                float v = s * (1.0f/S_N) - sMP[i]*sMP[j];
                if (i == j) v += sm[O_QD + i];
                sA[i*LP + j] = v;
            }
            __syncthreads();

            chol64(sA, sBI, T48, T32, T16, tid);     // sA = Lp, sBI diag = invL_JJ
            triinv64(sA, sBI, sG, tid);              // sBI = Lp^{-1}

            // phase A: u = Lp^{-1} m_p  +  write P_p_chol output (Lp in sA)
            if (tid < L_N) {
                const float* row = sBI + tid*LP;
                float s = 0.0f;
                #pragma unroll 4
                for (int j = 0; j <= tid; ++j) s += row[j]*sMP[j];
                sU[tid] = s;
            }
            {
                float4* po4 = (float4*)(out + OFF_PP + ((long long)(b*T_N + t))*L_N*L_N);
                for (int f = tid; f < 1024; f += NT) {
                    const int i = f >> 4, j0 = (f & 15) * 4;
                    float4 v;
                    v.x = (j0+0 <= i) ? sA[i*LP + j0+0] : 0.0f;
                    v.y = (j0+1 <= i) ? sA[i*LP + j0+1] : 0.0f;
                    v.z = (j0+2 <= i) ? sA[i*LP + j0+2] : 0.0f;
                    v.w = (j0+3 <= i) ? sA[i*LP + j0+3] : 0.0f;
                    po4[f] = v;
                }
            }
            __syncthreads();
            // phase B: h_f = Lp^{-T} u + k_t   and   J_f = BI^T BI + K K^T -> sA
            if (tid < L_N) {
                const float* col = sBI + tid;
                float s = 0.0f;
                #pragma unroll 4
                for (int k = tid; k < L_N; ++k) s += col[k*LP]*sU[k];
                sHF[tid] = s + sKV[tid];
            }
            for (int e = tid; e < TRIN; e += NT) {
                const uchar2 ij = T64[e];
                const int i = ij.x, j = ij.y;
                const float4* ki = (const float4*)(sKT + i*R_N);
                const float4* kj = (const float4*)(sKT + j*R_N);
                float acc = dot4(ki[0], kj[0]) + dot4(ki[1], kj[1])
                          + dot4(ki[2], kj[2]) + dot4(ki[3], kj[3]);
                const float* ci = sBI + i;
                const float* cj = sBI + j;
                int k = i;
                for (; k + 3 < L_N; k += 4) {
                    acc += ci[(k+0)*LP]*cj[(k+0)*LP] + ci[(k+1)*LP]*cj[(k+1)*LP]
                         + ci[(k+2)*LP]*cj[(k+2)*LP] + ci[(k+3)*LP]*cj[(k+3)*LP];
                }
                for (; k < L_N; ++k) acc += ci[k*LP]*cj[k*LP];
                sA[i*LP + j] = acc;
            }
            __syncthreads();
        }

        // ================= common tail: factor J_f, invert, outputs =================
        chol64(sA, sBI, T48, T32, T16, tid);    // sA = Lf
        triinv64(sA, sBI, sG, tid);             // sBI = Lf^{-1}

        // u2 = Lf^{-1} h_f
        if (tid < L_N) {
            const float* row = sBI + tid*LP;
            float s = 0.0f;
            #pragma unroll 4
            for (int j = 0; j <= tid; ++j) s += row[j]*sHF[j];
            sU[tid] = s;
        }
        __syncthreads();
        // m_f = Lf^{-T} u2 ; write m_p, m_f
        if (tid < L_N) {
            const float* col = sBI + tid;
            float s = 0.0f;
            #pragma unroll 4
            for (int k = tid; k < L_N; ++k) s += col[k*LP]*sU[k];
            sMF[tid] = s;
            out[OFF_MPo + ((long long)(b*T_N + t))*L_N + tid] = sMP[tid];
        }
        __syncthreads();
        if (tid < L_N)
            out[OFF_MFo + ((long long)(b*T_N + t))*L_N + tid] = sMF[tid];
        // P_f_chol = (Lf^{-1})^T (upper), zeros below
        {
            float4* po4 = (float4*)(out + OFF_PF + ((long long)(b*T_N + t))*L_N*L_N);
            for (int f = tid; f < 1024; f += NT) {
                const int i = f >> 4, j0 = (f & 15) * 4;
                float4 v;
                v.x = (j0+0 >= i) ? sBI[(j0+0)*LP + i] : 0.0f;
                v.y = (j0+1 >= i) ? sBI[(j0+1)*LP + i] : 0.0f;
                v.z = (j0+2 >= i) ? sBI[(j0+2)*LP + i] : 0.0f;
                v.w = (j0+3 >= i) ? sBI[(j0+3)*LP + i] : 0.0f;
                po4[f] = v;
            }
        }
        // z_f[s] = m_f + Pf_chol @ w_t[s]
        {
            const int i  = tid & 63;
            const int s0 = (tid >> 6) * 4;
            float z0 = sMF[i], z1 = z0, z2 = z0, z3 = z0;
            for (int j = i; j < L_N; ++j) {
                const float bv = sBI[j*LP + i];
                z0 += bv * sWT[(s0+0)*L_N + j];
                z1 += bv * sWT[(s0+1)*L_N + j];
                z2 += bv * sWT[(s0+2)*L_N + j];
                z3 += bv * sWT[(s0+3)*L_N + j];
            }
            sZ[(s0+0)*L_N + i] = z0;
            sZ[(s0+1)*L_N + i] = z1;
            sZ[(s0+2)*L_N + i] = z2;
            sZ[(s0+3)*L_N + i] = z3;
            out[((((long long)(s0+0))*B_N + b)*T_N + t)*L_N + i] = z0;
            out[((((long long)(s0+1))*B_N + b)*T_N + t)*L_N + i] = z1;
            out[((((long long)(s0+2))*B_N + b)*T_N + t)*L_N + i] = z2;
            out[((((long long)(s0+3))*B_N + b)*T_N + t)*L_N + i] = z3;
        }
        __syncthreads();
    }
}

extern "C" void kernel_launch(void* const* d_in, const int* in_sizes, int n_in,
                              void* d_out, int out_size) {
    const float* gk     = (const float*)d_in[0];
    const float* gK     = (const float*)d_in[1];
    const float* glogQ  = (const float*)d_in[2];
    const float* gm0    = (const float*)d_in[3];
    const float* glogv0 = (const float*)d_in[4];
    const float* gW1    = (const float*)d_in[5];
    const float* gb1    = (const float*)d_in[6];
    const float* gW2    = (const float*)d_in[7];
    const float* gb2    = (const float*)d_in[8];
    const float* gw     = (const float*)d_in[9];
    float* out = (float*)d_out;

    const size_t smem = (size_t)SMEM_BYTES;
    cudaFuncSetAttribute(nlf_kernel, cudaFuncAttributeMaxDynamicSharedMemorySize, (int)smem);
    nlf_kernel<<<B_N, NT, smem>>>(gk, gK, glogQ, gm0, glogv0, gW1, gb1, gW2, gb2, gw, out);
}

// round 6
// speedup vs baseline: 1.7869x; 1.0185x over previous
#include <cuda_runtime.h>
#include <math.h>

// Problem constants
#define S_N 16
#define B_N 128
#define T_N 200
#define L_N 64
#define R_N 16
#define H_N 256
#define NT  512
#define LP  68            // row stride for 64x64 mats: 16B-aligned rows
#define MTS 20            // transposed-m row stride
#define DIS 20            // diag-inverse block row stride
#define TRIN 2080

// ---- shared memory layout (float offsets) ----
#define O_W1  0
#define O_W2  (O_W1 + L_N*H_N)            // 16384
#define O_B1  (O_W2 + H_N*L_N)            // 32768
#define O_B2  (O_B1 + H_N)                // 33024
#define O_Z   (O_B2 + L_N)                // 33088
#define O_SCR (O_Z + S_N*L_N)             // 34112 : MLP hidden (4096) / G scratch (6*16*20=1920)
#define O_MT  (O_SCR + S_N*H_N)           // 38208 : m transposed [l][s]
#define O_A   (O_MT + L_N*MTS)            // 39488
#define O_BIT (O_A + L_N*LP)              // 43840 : transposed inverse BIT[i][k]=invL[k][i]
#define O_DI  (O_BIT + L_N*LP)            // 48192 : 4 diag-block inverses, normal layout
#define O_KT  (O_DI + 4*16*DIS)           // 49472
#define O_WT  (O_KT + L_N*R_N)            // 50496
#define O_MP  (O_WT + S_N*L_N)            // 51520
#define O_HF  (O_MP + L_N)
#define O_MF  (O_HF + L_N)
#define O_U   (O_MF + L_N)
#define O_KV  (O_U + L_N)
#define O_QD  (O_KV + L_N)
#define O_J0  (O_QD + L_N)
#define O_M0  (O_J0 + L_N)
#define O_SP  (O_M0 + L_N)
#define FLOAT_END (O_SP + L_N)
// index tables (bytes)
#define BYTE_T64 (FLOAT_END*4)
#define BYTE_T48 (BYTE_T64 + TRIN*2)
#define BYTE_T32 (BYTE_T48 + 1176*2)
#define BYTE_T16 (BYTE_T32 + 528*2)
#define SMEM_BYTES (BYTE_T16 + 136*2)

// ---- output offsets ----
#define OFF_ZF 0LL
#define OFF_MFo ((long long)S_N*B_N*T_N*L_N)
#define OFF_MPo (OFF_MFo + (long long)B_N*T_N*L_N)
#define OFF_PF  (OFF_MPo + (long long)B_N*T_N*L_N)
#define OFF_PP  (OFF_PF + (long long)B_N*T_N*L_N*L_N)

__device__ __forceinline__ void trimap(int e, int &i, int &j) {
    int ii = (int)((sqrtf(8.0f*(float)e + 1.0f) - 1.0f) * 0.5f);
    while ((ii+1)*(ii+2)/2 <= e) ++ii;
    while (ii*(ii+1)/2 > e) --ii;
    i = ii;
    j = e - ii*(ii+1)/2;
}

__device__ __forceinline__ float dot4(float4 a, float4 b) {
    return a.x*b.x + a.y*b.y + a.z*b.z + a.w*b.w;
}

// ---- warp-level 16x16 Cholesky + inverse (warp 0 only) ----
// Ad: diag block of A (stride LP) -> L written back (lower).
// DIb: normal-layout invL block (stride DIS).
// BITb: transposed invL written into BIT diag block (stride LP), zeros above.
__device__ __forceinline__ void warp_diag(float* Ad, float* DIb, float* BITb, int lane) {
    const int r = lane & 15;
    float a[16];
    #pragma unroll
    for (int k = 0; k < 16; ++k) a[k] = Ad[r*LP + k];
    float mydiag = 1.0f;
    #pragma unroll
    for (int c = 0; c < 16; ++c) {
        float dc = __shfl_sync(0xffffffffu, a[c], c);
        float rd = rsqrtf(dc);
        if (r >= c) a[c] *= rd;
        if (r == c) mydiag = a[c];
        #pragma unroll
        for (int k = c + 1; k < 16; ++k) {
            float lkc = __shfl_sync(0xffffffffu, a[c], k);
            if (r >= k) a[k] -= a[c] * lkc;
        }
    }
    const float invd = 1.0f / mydiag;
    if (lane < 16) {
        #pragma unroll
        for (int k = 0; k < 16; ++k)
            if (k <= r) Ad[r*LP + k] = a[k];
    }
    // lane c(=r) computes column c of X = invL ; x[rr] = X[rr][c], zero for c > rr
    float x[16];
    #pragma unroll
    for (int k = 0; k < 16; ++k) x[k] = 0.0f;
    #pragma unroll
    for (int rr = 0; rr < 16; ++rr) {
        float s = 0.0f;
        #pragma unroll
        for (int j = 0; j < 16; ++j) {
            if (j < rr) {
                float Lrj = __shfl_sync(0xffffffffu, a[j], rr);
                s += Lrj * x[j];
            }
        }
        float di = __shfl_sync(0xffffffffu, invd, rr);
        float v = ((r == rr ? 1.0f : 0.0f) - s) * di;
        x[rr] = (r <= rr) ? v : 0.0f;
    }
    if (lane < 16) {
        #pragma unroll
        for (int rr = 0; rr < 16; ++rr) DIb[rr*DIS + r] = x[rr];
        // transposed: BIT row r (within block) = x[0..15] (zeros where k<r)
        *(float4*)(BITb + r*LP + 0)  = make_float4(x[0],  x[1],  x[2],  x[3]);
        *(float4*)(BITb + r*LP + 4)  = make_float4(x[4],  x[5],  x[6],  x[7]);
        *(float4*)(BITb + r*LP + 8)  = make_float4(x[8],  x[9],  x[10], x[11]);
        *(float4*)(BITb + r*LP + 12) = make_float4(x[12], x[13], x[14], x[15]);
    }
}

// ---- blocked 64x64 Cholesky: sA -> L (lower); sDI/sBIT diag blocks -> invL_JJ ----
__device__ __noinline__ void chol64(float* sA, float* sBIT, float* sDI,
                                    const uchar2* T48, const uchar2* T32, const uchar2* T16,
                                    int tid) {
    const int lane = tid & 31;
    const int warp = tid >> 5;
    #pragma unroll 1
    for (int J = 0; J < 4; ++J) {
        if (warp == 0)
            warp_diag(sA + 16*J*(LP+1), sDI + J*16*DIS, sBIT + 16*J*(LP+1), lane);
        __syncthreads();
        if (J == 3) break;
        const int base = 16*(J+1);
        const int n = (64 - base) * 16;
        // panel: L[i][c] = sum_k A[i][16J+k] * invL_JJ[c][k]
        float pv[2];
        {
            int p = 0;
            #pragma unroll 1
            for (int e = tid; e < n; e += NT, ++p) {
                const int i = base + (e >> 4), c = e & 15;
                const float4* Ar = (const float4*)(sA + i*LP + 16*J);
                const float4* Xr = (const float4*)(sDI + J*16*DIS + c*DIS);
                pv[p] = dot4(Ar[0], Xr[0]) + dot4(Ar[1], Xr[1])
                      + dot4(Ar[2], Xr[2]) + dot4(Ar[3], Xr[3]);
            }
        }
        __syncthreads();
        {
            int p = 0;
            #pragma unroll 1
            for (int e = tid; e < n; e += NT, ++p) {
                const int i = base + (e >> 4), c = e & 15;
                sA[i*LP + 16*J + c] = pv[p];
            }
        }
        __syncthreads();
        // trailing update
        const uchar2* TT = (J == 0) ? T48 : (J == 1) ? T32 : T16;
        const int nt = (J == 0) ? 1176 : (J == 1) ? 528 : 136;
        #pragma unroll 1
        for (int e = tid; e < nt; e += NT) {
            const uchar2 lj = TT[e];
            const int i = base + lj.x, j = base + lj.y;
            const float4* Li = (const float4*)(sA + i*LP + 16*J);
            const float4* Lj = (const float4*)(sA + j*LP + 16*J);
            float acc = sA[i*LP + j];
            acc -= dot4(Li[0], Lj[0]) + dot4(Li[1], Lj[1])
                 + dot4(Li[2], Lj[2]) + dot4(Li[3], Lj[3]);
            sA[i*LP + j] = acc;
        }
        __syncthreads();
    }
}

// ---- blocked triangular inverse into TRANSPOSED storage:
// sBIT[i][k] = invL[k][i]. Requires sA=L, sDI=invL_JJ, sBIT diag blocks filled.
__device__ __noinline__ void triinv64(const float* sA, float* sBIT, float* sDI,
                                      float* G, int tid) {
    // G[blk][p][q] = sum_r invL_II[p][r] * L[16I+r][16K+q]   (stride DIS rows in G)
    #pragma unroll 1
    for (int e = tid; e < 1536; e += NT) {
        const int blk = e >> 8, p = (e >> 4) & 15, q = e & 15;
        int I, K;
        if      (blk == 0) { I = 1; K = 0; }
        else if (blk == 1) { I = 2; K = 0; }
        else if (blk == 2) { I = 2; K = 1; }
        else if (blk == 3) { I = 3; K = 0; }
        else if (blk == 4) { I = 3; K = 1; }
        else               { I = 3; K = 2; }
        const float4* xr = (const float4*)(sDI + I*16*DIS + p*DIS);
        float gv[16];
        *(float4*)(gv+0)  = xr[0]; *(float4*)(gv+4)  = xr[1];
        *(float4*)(gv+8)  = xr[2]; *(float4*)(gv+12) = xr[3];
        const float* Lc = sA + 16*I*LP + 16*K + q;
        float s = 0.0f;
        #pragma unroll
        for (int r = 0; r < 16; ++r) s += gv[r] * Lc[r*LP];
        G[blk*(16*DIS) + p*DIS + q] = s;
    }
    __syncthreads();
    // phase 1: X[I][I-1] = -G[I][I-1] * X[I-1][I-1]  (row-dot on BIT)
    #pragma unroll 1
    for (int e = tid; e < 768; e += NT) {
        const int b = e >> 8, p = e & 15, q = (e >> 4) & 15;
        const int I = b + 1, Jb = b;
        const int gi = I*(I-1)/2 + (I-1);
        const float4* g4 = (const float4*)(G + gi*(16*DIS) + p*DIS);
        const float4* x4 = (const float4*)(sBIT + (16*Jb + q)*LP + 16*Jb);
        float s = dot4(g4[0], x4[0]) + dot4(g4[1], x4[1])
                + dot4(g4[2], x4[2]) + dot4(g4[3], x4[3]);
        sBIT[(16*Jb + q)*LP + 16*I + p] = -s;
    }
    __syncthreads();
    // phase 2: X[2][0], X[3][1]
    #pragma unroll 1
    for (int e = tid; e < 512; e += NT) {
        const int b = e >> 8, p = e & 15, q = (e >> 4) & 15;
        const int I = (b == 0) ? 2 : 3, Jb = (b == 0) ? 0 : 1;
        float s = 0.0f;
        #pragma unroll
        for (int K = 0; K < 2; ++K) {
            const int Kb = Jb + K;
            const float4* g4 = (const float4*)(G + (I*(I-1)/2 + Kb)*(16*DIS) + p*DIS);
            const float4* x4 = (const float4*)(sBIT + (16*Jb + q)*LP + 16*Kb);
            s += dot4(g4[0], x4[0]) + dot4(g4[1], x4[1])
               + dot4(g4[2], x4[2]) + dot4(g4[3], x4[3]);
        }
        sBIT[(16*Jb + q)*LP + 16*I + p] = -s;
    }
    __syncthreads();
    // phase 3: X[3][0]
    #pragma unroll 1
    for (int e = tid; e < 256; e += NT) {
        const int p = e & 15, q = (e >> 4) & 15;
        float s = 0.0f;
        #pragma unroll
        for (int Kb = 0; Kb < 3; ++Kb) {
            const float4* g4 = (const float4*)(G + (3 + Kb)*(16*DIS) + p*DIS);
            const float4* x4 = (const float4*)(sBIT + q*LP + 16*Kb);
            s += dot4(g4[0], x4[0]) + dot4(g4[1], x4[1])
               + dot4(g4[2], x4[2]) + dot4(g4[3], x4[3]);
        }
        sBIT[q*LP + 48 + p] = -s;
    }
    __syncthreads();
}

__global__ void __launch_bounds__(NT, 1)
nlf_kernel(const float* __restrict__ gk,  const float* __restrict__ gK,
           const float* __restrict__ glogQ, const float* __restrict__ gm0,
           const float* __restrict__ glogv0, const float* __restrict__ gW1,
           const float* __restrict__ gb1, const float* __restrict__ gW2,
           const float* __restrict__ gb2, const float* __restrict__ gw,
           float* __restrict__ out)
{
    extern __shared__ float sm[];
    const int tid = threadIdx.x;
    const int b   = blockIdx.x;

    uchar2* const T64 = (uchar2*)((char*)sm + BYTE_T64);
    uchar2* const T48 = (uchar2*)((char*)sm + BYTE_T48);
    uchar2* const T32 = (uchar2*)((char*)sm + BYTE_T32);
    uchar2* const T16 = (uchar2*)((char*)sm + BYTE_T16);

    // ---- one-time setup ----
    {
        const float4* g1 = (const float4*)gW1;
        float4* s1 = (float4*)(sm + O_W1);
        for (int i = tid; i < L_N*H_N/4; i += NT) s1[i] = g1[i];
        const float4* g2 = (const float4*)gW2;
        float4* s2 = (float4*)(sm + O_W2);
        for (int i = tid; i < H_N*L_N/4; i += NT) s2[i] = g2[i];
        if (tid < H_N) sm[O_B1 + tid] = gb1[tid];
        if (tid < L_N) {
            sm[O_B2 + tid] = gb2[tid];
            float q = glogQ[tid], v = glogv0[tid];
            float qd = fmaxf(q, 0.f) + log1pf(expf(-fabsf(q)));
            float p0 = fmaxf(v, 0.f) + log1pf(expf(-fabsf(v)));
            sm[O_QD + tid] = qd;
            sm[O_J0 + tid] = 1.0f / p0;
            sm[O_SP + tid] = sqrtf(p0);
            sm[O_M0 + tid] = gm0[tid];
        }
        for (int e = tid; e < TRIN; e += NT) { int i, j; trimap(e, i, j); T64[e] = make_uchar2((unsigned char)i, (unsigned char)j); }
        for (int e = tid; e < 1176; e += NT) { int i, j; trimap(e, i, j); T48[e] = make_uchar2((unsigned char)i, (unsigned char)j); }
        for (int e = tid; e < 528;  e += NT) { int i, j; trimap(e, i, j); T32[e] = make_uchar2((unsigned char)i, (unsigned char)j); }
        for (int e = tid; e < 136;  e += NT) { int i, j; trimap(e, i, j); T16[e] = make_uchar2((unsigned char)i, (unsigned char)j); }
    }
    __syncthreads();

    float* const sZ   = sm + O_Z;
    float* const sHID = sm + O_SCR;
    float* const sG   = sm + O_SCR;
    float* const sMT  = sm + O_MT;
    float* const sA   = sm + O_A;
    float* const sBIT = sm + O_BIT;
    float* const sDI  = sm + O_DI;
    float* const sKT  = sm + O_KT;
    float* const sWT  = sm + O_WT;
    float* const sMP  = sm + O_MP;
    float* const sHF  = sm + O_HF;
    float* const sMF  = sm + O_MF;
    float* const sU   = sm + O_U;
    float* const sKV  = sm + O_KV;

    #pragma unroll 1
    for (int t = 0; t < T_N; ++t) {
        // ---- stage K_t, w_t, k_t ----
        {
            const float4* gkt = (const float4*)(gK + ((long long)(b*T_N + t))*L_N*R_N);
            float4* s4 = (float4*)sKT;
            for (int i = tid; i < L_N*R_N/4; i += NT) s4[i] = gkt[i];
            if (tid < 256) {
                const int ss = tid >> 4;
                const int l4 = (tid & 15) * 4;
                const float4 wv = *(const float4*)(gw + (((long long)t*S_N + ss)*B_N + b)*L_N + l4);
                *(float4*)(sWT + ss*L_N + l4) = wv;
            }
            if (tid < L_N) sKV[tid] = gk[((long long)(b*T_N + t))*L_N + tid];
        }
        __syncthreads();

        if (t == 0) {
            if (tid < L_N) {
                sMP[tid] = sm[O_M0 + tid];
                sHF[tid] = sm[O_J0 + tid]*sm[O_M0 + tid] + sKV[tid];
            }
            // P_p_chol[0] = diag(sqrt(P0))
            {
                float4* po4 = (float4*)(out + OFF_PP + ((long long)(b*T_N + t))*L_N*L_N);
                for (int f = tid; f < 1024; f += NT) {
                    const int i = f >> 4, j0 = (f & 15) * 4;
                    float4 v;
                    v.x = (j0+0 == i) ? sm[O_SP + i] : 0.0f;
                    v.y = (j0+1 == i) ? sm[O_SP + i] : 0.0f;
                    v.z = (j0+2 == i) ? sm[O_SP + i] : 0.0f;
                    v.w = (j0+3 == i) ? sm[O_SP + i] : 0.0f;
                    po4[f] = v;
                }
            }
            // J_f = diag(J0) + K0 K0^T
            for (int e = tid; e < TRIN; e += NT) {
                const uchar2 ij = T64[e];
                const int i = ij.x, j = ij.y;
                const float4* ki = (const float4*)(sKT + i*R_N);
                const float4* kj = (const float4*)(sKT + j*R_N);
                float s = dot4(ki[0], kj[0]) + dot4(ki[1], kj[1])
                        + dot4(ki[2], kj[2]) + dot4(ki[3], kj[3]);
                if (i == j) s += sm[O_J0 + i];
                sA[i*LP + j] = s;
            }
            __syncthreads();
        } else {
            // ---- MLP layer 1: 2 threads per hidden unit (8 samples each) ----
            {
                const int h  = tid >> 1;
                const int sb = (tid & 1) * 8;
                float acc[8];
                const float bb1 = sm[O_B1 + h];
                #pragma unroll
                for (int s = 0; s < 8; ++s) acc[s] = bb1;
                #pragma unroll 4
                for (int l = 0; l < L_N; l += 4) {
                    const float w0 = sm[O_W1 + (l+0)*H_N + h];
                    const float w1 = sm[O_W1 + (l+1)*H_N + h];
                    const float w2 = sm[O_W1 + (l+2)*H_N + h];
                    const float w3 = sm[O_W1 + (l+3)*H_N + h];
                    #pragma unroll
                    for (int s = 0; s < 8; ++s) {
                        float4 z4 = *(const float4*)(sZ + (sb+s)*L_N + l);
                        acc[s] += z4.x*w0 + z4.y*w1 + z4.z*w2 + z4.w*w3;
                    }
                }
                #pragma unroll
                for (int s = 0; s < 8; ++s) sHID[(sb+s)*H_N + h] = tanhf(acc[s]);
            }
            __syncthreads();
            // ---- MLP layer 2: 2 samples per thread -> sMT transposed [l][s] ----
            {
                const int lo = tid & 63;
                const int s0 = (tid >> 6) * 2;
                const float bb2 = sm[O_B2 + lo];
                float a0 = bb2, a1 = bb2;
                #pragma unroll 4
                for (int h = 0; h < H_N; h += 4) {
                    const float w0 = sm[O_W2 + (h+0)*L_N + lo];
                    const float w1 = sm[O_W2 + (h+1)*L_N + lo];
                    const float w2 = sm[O_W2 + (h+2)*L_N + lo];
                    const float w3 = sm[O_W2 + (h+3)*L_N + lo];
                    float4 h0 = *(const float4*)(sHID + (s0+0)*H_N + h);
                    float4 h1 = *(const float4*)(sHID + (s0+1)*H_N + h);
                    a0 += h0.x*w0 + h0.y*w1 + h0.z*w2 + h0.w*w3;
                    a1 += h1.x*w0 + h1.y*w1 + h1.z*w2 + h1.w*w3;
                }
                *(float2*)(sMT + lo*MTS + s0) = make_float2(a0, a1);
            }
            __syncthreads();
            // ---- m_p ----
            if (tid < L_N) {
                const float4* mr = (const float4*)(sMT + tid*MTS);
                float4 m0v = mr[0], m1v = mr[1], m2v = mr[2], m3v = mr[3];
                sMP[tid] = (m0v.x+m0v.y+m0v.z+m0v.w + m1v.x+m1v.y+m1v.z+m1v.w
                          + m2v.x+m2v.y+m2v.z+m2v.w + m3v.x+m3v.y+m3v.z+m3v.w) * (1.0f/S_N);
            }
            __syncthreads();
            // ---- P_p build ----
            for (int e = tid; e < TRIN; e += NT) {
                const uchar2 ij = T64[e];
                const int i = ij.x, j = ij.y;
                const float4* mi = (const float4*)(sMT + i*MTS);
                const float4* mj = (const float4*)(sMT + j*MTS);
                float s = dot4(mi[0], mj[0]) + dot4(mi[1], mj[1])
                        + dot4(mi[2], mj[2]) + dot4(mi[3], mj[3]);
                float v = s * (1.0f/S_N) - sMP[i]*sMP[j];
                if (i == j) v += sm[O_QD + i];
                sA[i*LP + j] = v;
            }
            __syncthreads();

            chol64(sA, sBIT, sDI, T48, T32, T16, tid);   // sA = Lp
            triinv64(sA, sBIT, sDI, sG, tid);            // sBIT = (Lp^{-1})^T rows

            // phase A: u = Lp^{-1} m_p (8 lanes/row) + write P_p_chol (Lp in sA)
            {
                const int i = tid >> 3, r = tid & 7;
                float s = 0.0f;
                for (int j = r; j <= i; j += 8) s += sBIT[j*LP + i] * sMP[j];
                s += __shfl_down_sync(0xffffffffu, s, 4, 8);
                s += __shfl_down_sync(0xffffffffu, s, 2, 8);
                s += __shfl_down_sync(0xffffffffu, s, 1, 8);
                if (r == 0) sU[i] = s;
            }
            {
                float4* po4 = (float4*)(out + OFF_PP + ((long long)(b*T_N + t))*L_N*L_N);
                for (int f = tid; f < 1024; f += NT) {
                    const int i = f >> 4, j0 = (f & 15) * 4;
                    float4 v;
                    v.x = (j0+0 <= i) ? sA[i*LP + j0+0] : 0.0f;
                    v.y = (j0+1 <= i) ? sA[i*LP + j0+1] : 0.0f;
                    v.z = (j0+2 <= i) ? sA[i*LP + j0+2] : 0.0f;
                    v.w = (j0+3 <= i) ? sA[i*LP + j0+3] : 0.0f;
                    po4[f] = v;
                }
            }
            __syncthreads();
            // phase B: h_f = Lp^{-T} u + k_t  and  J_f = BI^T BI + K K^T -> sA
            {
                const int i = tid >> 3, r = tid & 7;
                float s = 0.0f;
                for (int k = i + r; k < L_N; k += 8) s += sBIT[i*LP + k] * sU[k];
                s += __shfl_down_sync(0xffffffffu, s, 4, 8);
                s += __shfl_down_sync(0xffffffffu, s, 2, 8);
                s += __shfl_down_sync(0xffffffffu, s, 1, 8);
                if (r == 0) sHF[i] = s + sKV[i];
            }
            for (int e = tid; e < TRIN; e += NT) {
                const uchar2 ij = T64[e];
                const int i = ij.x, j = ij.y;   // i >= j
                const float4* ki = (const float4*)(sKT + i*R_N);
                const float4* kj = (const float4*)(sKT + j*R_N);
                float acc = dot4(ki[0], kj[0]) + dot4(ki[1], kj[1])
                          + dot4(ki[2], kj[2]) + dot4(ki[3], kj[3]);
                const float4* bi = (const float4*)(sBIT + i*LP);
                const float4* bj = (const float4*)(sBIT + j*LP);
                #pragma unroll 2
                for (int k4 = (i >> 2); k4 < 16; ++k4)
                    acc += dot4(bi[k4], bj[k4]);
                sA[i*LP + j] = acc;
            }
            __syncthreads();
        }

        // ================= common tail: factor J_f, invert, outputs =================
        chol64(sA, sBIT, sDI, T48, T32, T16, tid);   // sA = Lf
        triinv64(sA, sBIT, sDI, sG, tid);            // sBIT = (Lf^{-1})^T rows

        // u2 = Lf^{-1} h_f (8 lanes/row)
        {
            const int i = tid >> 3, r = tid & 7;
            float s = 0.0f;
            for (int j = r; j <= i; j += 8) s += sBIT[j*LP + i] * sHF[j];
            s += __shfl_down_sync(0xffffffffu, s, 4, 8);
            s += __shfl_down_sync(0xffffffffu, s, 2, 8);
            s += __shfl_down_sync(0xffffffffu, s, 1, 8);
            if (r == 0) sU[i] = s;
        }
        __syncthreads();
        // m_f = Lf^{-T} u2 ; write m_p
        {
            const int i = tid >> 3, r = tid & 7;
            float s = 0.0f;
            for (int k = i + r; k < L_N; k += 8) s += sBIT[i*LP + k] * sU[k];
            s += __shfl_down_sync(0xffffffffu, s, 4, 8);
            s += __shfl_down_sync(0xffffffffu, s, 2, 8);
            s += __shfl_down_sync(0xffffffffu, s, 1, 8);
            if (r == 0) sMF[i] = s;
        }
        if (tid < L_N)
            out[OFF_MPo + ((long long)(b*T_N + t))*L_N + tid] = sMP[tid];
        __syncthreads();
        if (tid < L_N)
            out[OFF_MFo + ((long long)(b*T_N + t))*L_N + tid] = sMF[tid];
        // P_f_chol = (Lf^{-1})^T (upper): row i of output = BIT row i, masked
        {
            float4* po4 = (float4*)(out + OFF_PF + ((long long)(b*T_N + t))*L_N*L_N);
            for (int f = tid; f < 1024; f += NT) {
                const int i = f >> 4, j0 = (f & 15) * 4;
                const float* bi = sBIT + i*LP;
                float4 v;
                v.x = (j0+0 >= i) ? bi[j0+0] : 0.0f;
                v.y = (j0+1 >= i) ? bi[j0+1] : 0.0f;
                v.z = (j0+2 >= i) ? bi[j0+2] : 0.0f;
                v.w = (j0+3 >= i) ? bi[j0+3] : 0.0f;
                po4[f] = v;
            }
        }
        // z_f[s] = m_f + Pf_chol @ w_t[s]  (row dots on BIT; 2 samples/thread)
        {
            const int i  = tid & 63;
            const int s0 = (tid >> 6) * 2;
            const int k0 = i >> 2;
            float z0 = sMF[i], z1 = z0;
            const float4* bi4 = (const float4*)(sBIT + i*LP);
            const float4* w04 = (const float4*)(sWT + (s0+0)*L_N);
            const float4* w14 = (const float4*)(sWT + (s0+1)*L_N);
            #pragma unroll 2
            for (int j4 = k0; j4 < 16; ++j4) {
                const float4 bv = bi4[j4];
                z0 += dot4(bv, w04[j4]);
                z1 += dot4(bv, w14[j4]);
            }
            sZ[(s0+0)*L_N + i] = z0;
            sZ[(s0+1)*L_N + i] = z1;
            out[((((long long)(s0+0))*B_N + b)*T_N + t)*L_N + i] = z0;
            out[((((long long)(s0+1))*B_N + b)*T_N + t)*L_N + i] = z1;
        }
        __syncthreads();
    }
}

extern "C" void kernel_launch(void* const* d_in, const int* in_sizes, int n_in,
                              void* d_out, int out_size) {
    const float* gk     = (const float*)d_in[0];
    const float* gK     = (const float*)d_in[1];
    const float* glogQ  = (const float*)d_in[2];
    const float* gm0    = (const float*)d_in[3];
    const float* glogv0 = (const float*)d_in[4];
    const float* gW1    = (const float*)d_in[5];
    const float* gb1    = (const float*)d_in[6];
    const float* gW2    = (const float*)d_in[7];
    const float* gb2    = (const float*)d_in[8];
    const float* gw     = (const float*)d_in[9];
    float* out = (float*)d_out;

    const size_t smem = (size_t)SMEM_BYTES;
    cudaFuncSetAttribute(nlf_kernel, cudaFuncAttributeMaxDynamicSharedMemorySize, (int)smem);
    nlf_kernel<<<B_N, NT, smem>>>(gk, gK, glogQ, gm0, glogv0, gW1, gb1, gW2, gb2, gw, out);
}